// round 11
// baseline (speedup 1.0000x reference)
#include <cuda_runtime.h>
#include <cstdint>

typedef unsigned long long ull;

// Problem constants
#define BATCH   512
#define OUTF    1024
#define KDIM    128      // NUM_BLOCKS * LATTICE_DIM
#define NIDX    256      // MAX_INDICES

// Tiling for main kernel
#define NSEG    8        // k-segments (grid.y)
#define KSEG    16       // k per segment
#define KCH     2        // k per staging chunk (per buffer)
#define NCH     (KSEG / KCH)       // 8 chunks
#define BT      32       // b per CTA
#define MTHREADS 1024    // 32 warps: warp w owns o = w*32 .. w*32+31
// buffer: [kk(2)][pair(16)][j(256)] float2 = 8192 f2 = 64 KB; double buffered = 128 KB
#define BUF_F2  8192

// Per-segment partials, [seg][o][b] (b contiguous): 16 MB
__device__ float g_part[NSEG][OUTF][BATCH];

__device__ __forceinline__ ull addf32x2(ull a, ull b) {
    ull r;
    asm("add.rn.f32x2 %0, %1, %2;" : "=l"(r) : "l"(a), "l"(b));
    return r;
}

// ---------------- main kernel: float2-paired, LDS.64 conflict-free gather ----------------
// CTA (btile, seg): b in [btile*32,+32), k in [seg*16,+16), all 1024 o.
// smem: S[buf][kk][p][ j ^ p ] : float2 = {row_{2p}[j], row_{2p+1}[j]}.
// Gather: lane l -> p = l&15, half = l>>4; lanes 0-15 gather o_A, 16-31 gather o_B.
// Each 16-lane phase hits distinct 8B banks (j^p distinct mod 16) -> conflict-free.
__global__ __launch_bounds__(MTHREADS, 1) void lut_main(
    const int*   __restrict__ inp,   // [BATCH, KDIM] int32
    const int*   __restrict__ wgt,   // [OUTF, KDIM]  int32
    const float* __restrict__ lut)   // [256, 256]
{
    extern __shared__ float2 S2[];   // 2 * BUF_F2 float2 = 128 KB
    ull* Su = (ull*)S2;

    const int btile = blockIdx.x;    // 0..15
    const int seg   = blockIdx.y;    // 0..7
    const int tid   = threadIdx.x;
    const int wid   = tid >> 5;
    const int lane  = tid & 31;
    const int p     = lane & 15;
    const int obase = wid * 32;

    // ---- fused pack: this lane's 16 weight indices (o = obase+lane) as 4 byte-words ----
    const int* wp = wgt + (obase + lane) * KDIM + seg * KSEG;
    unsigned jw0, jw1, jw2, jw3;
    {
        int4 v0 = ((const int4*)wp)[0];
        int4 v1 = ((const int4*)wp)[1];
        int4 v2 = ((const int4*)wp)[2];
        int4 v3 = ((const int4*)wp)[3];
        #define CLP(x) ((unsigned)min(max((x), 0), NIDX - 1))
        jw0 = CLP(v0.x) | (CLP(v0.y) << 8) | (CLP(v0.z) << 16) | (CLP(v0.w) << 24);
        jw1 = CLP(v1.x) | (CLP(v1.y) << 8) | (CLP(v1.z) << 16) | (CLP(v1.w) << 24);
        jw2 = CLP(v2.x) | (CLP(v2.y) << 8) | (CLP(v2.z) << 16) | (CLP(v2.w) << 24);
        jw3 = CLP(v3.x) | (CLP(v3.y) << 8) | (CLP(v3.z) << 16) | (CLP(v3.w) << 24);
        #undef CLP
    }
    const unsigned lx = (unsigned)p * 0x0101u;   // xor p into bytes 0,1

    // ---- staging role: warp = (kk = wid>>4, pair ps = wid&15): rows b=2ps, 2ps+1 ----
    const int kw = wid >> 4;
    const int ps = wid & 15;
    const int* ip0 = inp + (btile * BT + 2 * ps) * KDIM + seg * KSEG + kw;
    const int* ip1 = ip0 + KDIM;
    float2* drow = S2 + (kw * 16 + ps) * 256;       // + buf*BUF_F2 at use

    // gather base (8B units): block for (kk, p)
    const ull* Sg = Su + p * 256;                   // + (c&1)*BUF_F2 (+4096 for kk=1)

    ull acc[16];
    #pragma unroll
    for (int i = 0; i < 16; ++i) acc[i] = 0ull;

    // ---- prologue: stage chunk 0 into buffer 0 ----
    {
        int r0 = min(max(ip0[0], 0), NIDX - 1);
        int r1 = min(max(ip1[0], 0), NIDX - 1);
        const float* s0 = lut + r0 * 256;
        const float* s1 = lut + r1 * 256;
        #pragma unroll
        for (int t = 0; t < 8; ++t) {
            int j = t * 32 + lane;
            drow[j ^ ps] = make_float2(__ldg(s0 + j), __ldg(s1 + j));
        }
    }
    __syncthreads();

    // ---- pipelined chunks ----
    #pragma unroll 1
    for (int c = 0; c < NCH; ++c) {
        const bool more = (c < NCH - 1);
        const float* sA = lut;
        const float* sB = lut;
        if (more) {
            int r0 = min(max(ip0[(c + 1) * KCH], 0), NIDX - 1);
            int r1 = min(max(ip1[(c + 1) * KCH], 0), NIDX - 1);
            sA = lut + r0 * 256;
            sB = lut + r1 * 256;
        }

        const ull* Sb = Sg + (c & 1) * BUF_F2;
        unsigned word = (c < 2) ? jw0 : (c < 4) ? jw1 : (c < 6) ? jw2 : jw3;
        unsigned wv = word >> (16 * (c & 1));   // bytes 0,1 = kk0,kk1 of chunk c

        // LDG next rows (latency hides under first gather half)
        float rg0[8], rg1[8];
        if (more) {
            #pragma unroll
            for (int t = 0; t < 8; ++t) rg0[t] = __ldg(sA + t * 32 + lane);
            #pragma unroll
            for (int t = 0; t < 8; ++t) rg1[t] = __ldg(sB + t * 32 + lane);
        }

        // gather iterations 0..7: lanes 0-15 serve o=obase+i, lanes 16-31 o=obase+16+i
        #pragma unroll
        for (int i = 0; i < 8; ++i) {
            unsigned w = __shfl_sync(0xffffffffu, wv, i | (lane & 16)) ^ lx;
            ull v0 = Sb[w & 255u];
            ull v1 = Sb[4096 + ((w >> 8) & 255u)];
            acc[i] = addf32x2(acc[i], addf32x2(v0, v1));
        }

        // STS next chunk rows (both rows loaded; conflict-free 16-lane phases)
        if (more) {
            float2* d = drow + ((c + 1) & 1) * BUF_F2;
            #pragma unroll
            for (int t = 0; t < 8; ++t)
                d[(t * 32 + lane) ^ ps] = make_float2(rg0[t], rg1[t]);
        }

        // gather iterations 8..15
        #pragma unroll
        for (int i = 8; i < 16; ++i) {
            unsigned w = __shfl_sync(0xffffffffu, wv, i | (lane & 16)) ^ lx;
            ull v0 = Sb[w & 255u];
            ull v1 = Sb[4096 + ((w >> 8) & 255u)];
            acc[i] = addf32x2(acc[i], addf32x2(v0, v1));
        }

        __syncthreads();
    }

    // ---- partial store: acc[i] = (o = obase + i + (lane&16), b = 2p, 2p+1), STG.64 ----
    #pragma unroll
    for (int i = 0; i < 16; ++i) {
        int row_o = obase + i + (lane & 16);
        *(ull*)&g_part[seg][row_o][btile * BT + 2 * p] = acc[i];
    }
}

// ---------------- epilogue: high-occupancy seg-split transpose-reduce ----------------
// 2048 blocks x 128 threads; tile = 8 o x 32 b; thread: 1 o x 4 b (float4) x 4 segs;
// two seg-halves combined through smem.
__global__ __launch_bounds__(128) void reduce_kernel(float* __restrict__ out) {
    __shared__ float st[2][8][36];     // [half][o][b], pitch 36: warp-conflict-free
    const int o0 = blockIdx.x * 8;
    const int b0 = blockIdx.y * 32;
    const int t  = threadIdx.x;
    const int h  = t >> 6;             // seg half
    const int r  = t & 63;
    const int oi = r >> 3;             // 0..7
    const int bq = r & 7;              // 0..7 -> b offset 4*bq

    float4 a = make_float4(0.f, 0.f, 0.f, 0.f);
    #pragma unroll
    for (int s = 0; s < 4; ++s) {      // 4 independent coalesced float4 loads
        float4 v = *(const float4*)&g_part[4 * h + s][o0 + oi][b0 + 4 * bq];
        a.x += v.x; a.y += v.y; a.z += v.z; a.w += v.w;
    }
    *(float4*)&st[h][oi][4 * bq] = a;
    __syncthreads();

    const int oi2 = t & 7;
    const int bb  = t >> 3;            // 0..15
    out[(b0 + bb) * OUTF + o0 + oi2]      = st[0][oi2][bb]      + st[1][oi2][bb];
    out[(b0 + bb + 16) * OUTF + o0 + oi2] = st[0][oi2][bb + 16] + st[1][oi2][bb + 16];
}

// ---------------- launch ----------------
extern "C" void kernel_launch(void* const* d_in, const int* in_sizes, int n_in,
                              void* d_out, int out_size) {
    const int*   inp = (const int*)d_in[0];    // input_indices  [512,32,4]
    const int*   wgt = (const int*)d_in[1];    // weight_indices [1024,32,4]
    const float* lut = (const float*)d_in[2];  // lut_table [256,256]
    float* out = (float*)d_out;

    const int smem_bytes = 2 * BUF_F2 * (int)sizeof(float2);  // 128 KB
    cudaFuncSetAttribute(lut_main, cudaFuncAttributeMaxDynamicSharedMemorySize, smem_bytes);
    dim3 grid(BATCH / BT, NSEG);
    lut_main<<<grid, MTHREADS, smem_bytes>>>(inp, wgt, lut);

    reduce_kernel<<<dim3(OUTF / 8, BATCH / 32), 128>>>(out);
}